// round 1
// baseline (speedup 1.0000x reference)
#include <cuda_runtime.h>

// Problem dims
#define Bsz   2
#define Ssz   2048
#define Hsz   2048
#define NHEAD 16
#define HDIM  128
#define Mrows (Bsz*Ssz)   // 4096

// Scratch (static device globals: allowed; no dynamic allocation anywhere)
__device__ float g_Q [Mrows*Hsz];
__device__ float g_K [Mrows*Hsz];
__device__ float g_V [Mrows*Hsz];
__device__ float g_AO[Mrows*Hsz];

typedef unsigned long long u64;

// ---- packed f32x2 helpers (Blackwell sm_100a) ----
__device__ __forceinline__ u64 dup2(float v) {
    u64 r; asm("mov.b64 %0, {%1, %1};" : "=l"(r) : "f"(v)); return r;
}
__device__ __forceinline__ void upk2(u64 v, float& lo, float& hi) {
    asm("mov.b64 {%0, %1}, %2;" : "=f"(lo), "=f"(hi) : "l"(v));
}
__device__ __forceinline__ void ffma2(u64& d, u64 a, u64 b) {
    asm("fma.rn.f32x2 %0, %1, %2, %0;" : "+l"(d) : "l"(a), "l"(b));
}
__device__ __forceinline__ void fmul2(u64& d, u64 a) {
    asm("mul.rn.f32x2 %0, %0, %1;" : "+l"(d) : "l"(a));
}

// ============================================================
// SGEMM: C[m,n] = sum_k A[m,k]*B[n,k] + bias[n]
// (A: [M,K] row-major, B: [N,K] row-major == torch Linear weight)
// 128x128 tile, BK=16, 256 threads, 8x8 per thread (f32x2 packed).
// ============================================================
#define SGK   16
#define SGPAD 132

__global__ void __launch_bounds__(256, 2)
sgemm_abt_bias(const float* __restrict__ A, const float* __restrict__ Bm,
               const float* __restrict__ bias, float* __restrict__ C,
               int M, int N, int K)
{
    __shared__ float As[SGK][SGPAD];
    __shared__ float Bs[SGK][SGPAD];
    const int tid = threadIdx.x;
    const int bm = blockIdx.y * 128;
    const int bn = blockIdx.x * 128;
    const int ty = tid >> 4;          // 0..15 -> row groups
    const int tx = tid & 15;          // 0..15 -> col groups
    const int lrow = tid >> 2;        // 0..63
    const int lc4  = (tid & 3) << 2;  // 0,4,8,12

    u64 acc[8][4];
    #pragma unroll
    for (int i = 0; i < 8; i++)
        #pragma unroll
        for (int j = 0; j < 4; j++) acc[i][j] = 0ull;

    for (int kt = 0; kt < K; kt += SGK) {
        #pragma unroll
        for (int h2 = 0; h2 < 2; h2++) {
            int row = lrow + h2 * 64;
            float4 va = *(const float4*)(A  + (size_t)(bm + row) * K + kt + lc4);
            As[lc4+0][row] = va.x; As[lc4+1][row] = va.y;
            As[lc4+2][row] = va.z; As[lc4+3][row] = va.w;
            float4 vb = *(const float4*)(Bm + (size_t)(bn + row) * K + kt + lc4);
            Bs[lc4+0][row] = vb.x; Bs[lc4+1][row] = vb.y;
            Bs[lc4+2][row] = vb.z; Bs[lc4+3][row] = vb.w;
        }
        __syncthreads();
        #pragma unroll
        for (int k = 0; k < SGK; k++) {
            // rows: {ty*4+i} and {64+ty*4+i}; cols: {tx*4+j} and {64+tx*4+j}
            float4 a0 = *(const float4*)&As[k][ty * 4];
            float4 a1 = *(const float4*)&As[k][64 + ty * 4];
            ulonglong2 b0 = *(const ulonglong2*)&Bs[k][tx * 4];
            ulonglong2 b1 = *(const ulonglong2*)&Bs[k][64 + tx * 4];
            float av[8] = {a0.x, a0.y, a0.z, a0.w, a1.x, a1.y, a1.z, a1.w};
            u64 bv[4]   = {b0.x, b0.y, b1.x, b1.y};
            #pragma unroll
            for (int i = 0; i < 8; i++) {
                u64 ad = dup2(av[i]);
                #pragma unroll
                for (int j = 0; j < 4; j++) ffma2(acc[i][j], ad, bv[j]);
            }
        }
        __syncthreads();
    }
    #pragma unroll
    for (int i = 0; i < 8; i++) {
        int row = bm + ((i < 4) ? (ty * 4 + i) : (64 + ty * 4 + i - 4));
        #pragma unroll
        for (int half = 0; half < 2; half++) {
            int col = bn + half * 64 + tx * 4;
            float4 v;
            upk2(acc[i][half * 2 + 0], v.x, v.y);
            upk2(acc[i][half * 2 + 1], v.z, v.w);
            v.x += bias[col + 0]; v.y += bias[col + 1];
            v.z += bias[col + 2]; v.w += bias[col + 3];
            *(float4*)(C + (size_t)row * N + col) = v;
        }
    }
}

// ============================================================
// Flash attention, fp32, causal. BQ=BKV=64, D=128, 256 threads.
// Q/K/V/O global layout: [B*S, H] with head offset h*128 (no transpose).
// K and V share one smem buffer (sequenced by syncthreads).
// ============================================================
#define KST 66   // transposed-K smem stride (even -> 8B-aligned u64 pair loads)

__global__ void __launch_bounds__(256, 2)
flash_attn(const float* __restrict__ Qg, const float* __restrict__ Kg,
           const float* __restrict__ Vg, float* __restrict__ Og)
{
    extern __shared__ float sm[];
    float* sQ  = sm;                   // [64][128] row-major
    float* sKV = sm + 64 * 128;        // K as [128][KST] transposed, or V as [64][128]
    float* sP  = sKV + 128 * KST;      // [64][64]

    const int tid = threadIdx.x;
    const int tx = tid & 15;
    const int ty = tid >> 4;
    const int qb = blockIdx.x;
    const int h  = blockIdx.y;
    const int b  = blockIdx.z;
    const int q0 = qb * 64;
    const size_t base = (size_t)b * Ssz * Hsz + (size_t)h * HDIM;

    // load Q tile (coalesced float4)
    for (int i = tid * 4; i < 64 * 128; i += 1024) {
        int r = i >> 7, d = i & 127;
        *(float4*)&sQ[i] = *(const float4*)&Qg[base + (size_t)(q0 + r) * Hsz + d];
    }

    u64 o2[4][4];             // rows ty*4+i; col pairs {tx*4+0,1},{+2,3},{64+tx*4+0,1},{+2,3}
    #pragma unroll
    for (int i = 0; i < 4; i++)
        #pragma unroll
        for (int j = 0; j < 4; j++) o2[i][j] = 0ull;
    float m_i[4], l_i[4];
    #pragma unroll
    for (int i = 0; i < 4; i++) { m_i[i] = -1e30f; l_i[i] = 0.f; }

    for (int kt = 0; kt <= qb; kt++) {
        __syncthreads();  // previous PV done before overwriting sKV/sP
        // load K transposed: sKV[d][j]
        for (int i = tid; i < 64 * 128; i += 256) {
            int r = i >> 7, d = i & 127;
            sKV[d * KST + r] = Kg[base + (size_t)(kt * 64 + r) * Hsz + d];
        }
        __syncthreads();

        // S = Q K^T  (regs, f32x2 packed along j)
        u64 s2[4][2];
        #pragma unroll
        for (int i = 0; i < 4; i++) { s2[i][0] = 0ull; s2[i][1] = 0ull; }
        #pragma unroll 4
        for (int d = 0; d < 128; d++) {
            u64 k0 = *(const u64*)&sKV[d * KST + tx * 4];
            u64 k1 = *(const u64*)&sKV[d * KST + tx * 4 + 2];
            const float* qp = &sQ[(ty * 4) * 128 + d];
            #pragma unroll
            for (int i = 0; i < 4; i++) {
                u64 qd = dup2(qp[i * 128]);
                ffma2(s2[i][0], qd, k0);
                ffma2(s2[i][1], qd, k1);
            }
        }

        // unpack, scale, causal mask
        float s[4][4];
        const float sc = 0.08838834764831845f;  // 1/sqrt(128)
        #pragma unroll
        for (int i = 0; i < 4; i++) {
            upk2(s2[i][0], s[i][0], s[i][1]);
            upk2(s2[i][1], s[i][2], s[i][3]);
            #pragma unroll
            for (int j = 0; j < 4; j++) s[i][j] *= sc;
        }
        if (kt == qb) {
            #pragma unroll
            for (int i = 0; i < 4; i++)
                #pragma unroll
                for (int j = 0; j < 4; j++)
                    if (tx * 4 + j > ty * 4 + i) s[i][j] = -1e30f;
        }

        // online softmax (shuffle over the 16 tx lanes sharing each row)
        float fac[4];
        #pragma unroll
        for (int i = 0; i < 4; i++) {
            float rm = fmaxf(fmaxf(s[i][0], s[i][1]), fmaxf(s[i][2], s[i][3]));
            #pragma unroll
            for (int off = 8; off > 0; off >>= 1)
                rm = fmaxf(rm, __shfl_xor_sync(0xffffffffu, rm, off));
            float mn = fmaxf(m_i[i], rm);
            fac[i] = __expf(m_i[i] - mn);
            float rs = 0.f;
            #pragma unroll
            for (int j = 0; j < 4; j++) { s[i][j] = __expf(s[i][j] - mn); rs += s[i][j]; }
            #pragma unroll
            for (int off = 8; off > 0; off >>= 1)
                rs += __shfl_xor_sync(0xffffffffu, rs, off);
            l_i[i] = l_i[i] * fac[i] + rs;
            m_i[i] = mn;
        }

        // stage P, rescale O accumulators
        #pragma unroll
        for (int i = 0; i < 4; i++) {
            *(float4*)&sP[(ty * 4 + i) * 64 + tx * 4] =
                make_float4(s[i][0], s[i][1], s[i][2], s[i][3]);
            u64 fd = dup2(fac[i]);
            #pragma unroll
            for (int j = 0; j < 4; j++) fmul2(o2[i][j], fd);
        }
        __syncthreads();

        // load V row-major into the shared K/V buffer
        for (int i = tid * 4; i < 64 * 128; i += 1024) {
            int r = i >> 7, d = i & 127;
            *(float4*)&sKV[r * 128 + d] =
                *(const float4*)&Vg[base + (size_t)(kt * 64 + r) * Hsz + d];
        }
        __syncthreads();

        // O += P V
        #pragma unroll 2
        for (int j = 0; j < 64; j++) {
            ulonglong2 v0 = *(const ulonglong2*)&sKV[j * 128 + tx * 4];
            ulonglong2 v1 = *(const ulonglong2*)&sKV[j * 128 + 64 + tx * 4];
            const float* pp = &sP[(ty * 4) * 64 + j];
            #pragma unroll
            for (int i = 0; i < 4; i++) {
                u64 pd = dup2(pp[i * 64]);
                ffma2(o2[i][0], pd, v0.x);
                ffma2(o2[i][1], pd, v0.y);
                ffma2(o2[i][2], pd, v1.x);
                ffma2(o2[i][3], pd, v1.y);
            }
        }
    }

    // epilogue: normalize and store
    #pragma unroll
    for (int i = 0; i < 4; i++) {
        float inv = 1.0f / l_i[i];
        size_t rowoff = base + (size_t)(q0 + ty * 4 + i) * Hsz;
        float4 w;
        upk2(o2[i][0], w.x, w.y); upk2(o2[i][1], w.z, w.w);
        w.x *= inv; w.y *= inv; w.z *= inv; w.w *= inv;
        *(float4*)&Og[rowoff + tx * 4] = w;
        upk2(o2[i][2], w.x, w.y); upk2(o2[i][3], w.z, w.w);
        w.x *= inv; w.y *= inv; w.z *= inv; w.w *= inv;
        *(float4*)&Og[rowoff + 64 + tx * 4] = w;
    }
}

// ============================================================
extern "C" void kernel_launch(void* const* d_in, const int* in_sizes, int n_in,
                              void* d_out, int out_size) {
    const float* x  = (const float*)d_in[0];
    const float* WQ = (const float*)d_in[1];
    const float* bQ = (const float*)d_in[2];
    const float* WK = (const float*)d_in[3];
    const float* bK = (const float*)d_in[4];
    const float* WV = (const float*)d_in[5];
    const float* bV = (const float*)d_in[6];
    const float* WO = (const float*)d_in[7];
    const float* bO = (const float*)d_in[8];
    float* out = (float*)d_out;

    float *qp, *kp, *vp, *ap;
    cudaGetSymbolAddress((void**)&qp, g_Q);
    cudaGetSymbolAddress((void**)&kp, g_K);
    cudaGetSymbolAddress((void**)&vp, g_V);
    cudaGetSymbolAddress((void**)&ap, g_AO);

    dim3 gg(Hsz / 128, Mrows / 128);
    sgemm_abt_bias<<<gg, 256>>>(x, WQ, bQ, qp, Mrows, Hsz, Hsz);
    sgemm_abt_bias<<<gg, 256>>>(x, WK, bK, kp, Mrows, Hsz, Hsz);
    sgemm_abt_bias<<<gg, 256>>>(x, WV, bV, vp, Mrows, Hsz, Hsz);

    const int smbytes = (64 * 128 + 128 * KST + 64 * 64) * 4;  // ~83 KB
    cudaFuncSetAttribute(flash_attn, cudaFuncAttributeMaxDynamicSharedMemorySize, smbytes);
    flash_attn<<<dim3(Ssz / 64, NHEAD, Bsz), 256, smbytes>>>(qp, kp, vp, ap);

    sgemm_abt_bias<<<gg, 256>>>(ap, WO, bO, out, Mrows, Hsz, Hsz);
}

// round 3
// speedup vs baseline: 1.5946x; 1.5946x over previous
#include <cuda_runtime.h>
#include <cuda_bf16.h>
#include <cstdint>

// Problem dims
#define Bsz   2
#define Ssz   2048
#define Hsz   2048
#define NHEAD 16
#define HDIM  128
#define Mrows (Bsz*Ssz)   // 4096

// ---------------- scratch (static device globals) ----------------
__device__ float g_Q [Mrows*Hsz];
__device__ float g_K [Mrows*Hsz];
__device__ float g_V [Mrows*Hsz];
__device__ float g_AO[Mrows*Hsz];

__device__ __nv_bfloat16 g_xh[Mrows*Hsz], g_xl[Mrows*Hsz];
__device__ __nv_bfloat16 g_aoh[Mrows*Hsz], g_aol[Mrows*Hsz];
__device__ __nv_bfloat16 g_wh[4][Hsz*Hsz], g_wl[4][Hsz*Hsz];

typedef unsigned long long u64;

// ---------------- helpers ----------------
__device__ __forceinline__ uint32_t smem_u32(const void* p) {
    uint32_t a;
    asm("{ .reg .u64 t; cvta.to.shared.u64 t, %1; cvt.u32.u64 %0, t; }" : "=r"(a) : "l"(p));
    return a;
}
#define CP_ASYNC16(sa, ga) \
    asm volatile("cp.async.cg.shared.global [%0], [%1], 16;" :: "r"((uint32_t)(sa)), "l"(ga))
#define CP_COMMIT() asm volatile("cp.async.commit_group;" ::: "memory")
#define CP_WAIT(n)  asm volatile("cp.async.wait_group %0;" :: "n"(n) : "memory")

__device__ __forceinline__ void ldsm4(uint32_t* r, uint32_t addr) {
    asm volatile("ldmatrix.sync.aligned.m8n8.x4.shared.b16 {%0,%1,%2,%3}, [%4];"
                 : "=r"(r[0]), "=r"(r[1]), "=r"(r[2]), "=r"(r[3]) : "r"(addr));
}
__device__ __forceinline__ void mma16816(float* c, const uint32_t* a,
                                         uint32_t b0, uint32_t b1) {
    asm volatile(
        "mma.sync.aligned.m16n8k16.row.col.f32.bf16.bf16.f32 "
        "{%0,%1,%2,%3}, {%4,%5,%6,%7}, {%8,%9}, {%0,%1,%2,%3};"
        : "+f"(c[0]), "+f"(c[1]), "+f"(c[2]), "+f"(c[3])
        : "r"(a[0]), "r"(a[1]), "r"(a[2]), "r"(a[3]), "r"(b0), "r"(b1));
}

// ---- packed f32x2 helpers (flash attention) ----
__device__ __forceinline__ u64 dup2(float v) {
    u64 r; asm("mov.b64 %0, {%1, %1};" : "=l"(r) : "f"(v)); return r;
}
__device__ __forceinline__ void upk2(u64 v, float& lo, float& hi) {
    asm("mov.b64 {%0, %1}, %2;" : "=f"(lo), "=f"(hi) : "l"(v));
}
__device__ __forceinline__ void ffma2(u64& d, u64 a, u64 b) {
    asm("fma.rn.f32x2 %0, %1, %2, %0;" : "+l"(d) : "l"(a), "l"(b));
}
__device__ __forceinline__ void fmul2(u64& d, u64 a) {
    asm("mul.rn.f32x2 %0, %0, %1;" : "+l"(d) : "l"(a));
}

// ============================================================
// split fp32 -> (bf16 hi, bf16 lo)
// ============================================================
__global__ void split_bf16(const float4* __restrict__ in,
                           __nv_bfloat162* __restrict__ hi,
                           __nv_bfloat162* __restrict__ lo, int n4)
{
    for (int i = blockIdx.x * blockDim.x + threadIdx.x; i < n4; i += gridDim.x * blockDim.x) {
        float4 v = in[i];
        __nv_bfloat16 h0 = __float2bfloat16(v.x), h1 = __float2bfloat16(v.y);
        __nv_bfloat16 h2 = __float2bfloat16(v.z), h3 = __float2bfloat16(v.w);
        __nv_bfloat16 l0 = __float2bfloat16(v.x - __bfloat162float(h0));
        __nv_bfloat16 l1 = __float2bfloat16(v.y - __bfloat162float(h1));
        __nv_bfloat16 l2 = __float2bfloat16(v.z - __bfloat162float(h2));
        __nv_bfloat16 l3 = __float2bfloat16(v.w - __bfloat162float(h3));
        hi[2*i]   = __nv_bfloat162(h0, h1); hi[2*i+1] = __nv_bfloat162(h2, h3);
        lo[2*i]   = __nv_bfloat162(l0, l1); lo[2*i+1] = __nv_bfloat162(l2, l3);
    }
}

// ============================================================
// mma.sync GEMM: C[4096, 2048] = A @ B^T + bias  (3-pass bf16 split)
// CTA tile 128(m) x 256(n), BK=32. 8 warps: 2(m) x 4(n), warp tile 64x64.
// Smem rows padded to 40 bf16 (80B = 20 banks -> ldmatrix conflict-free).
// ============================================================
#define LDR    40           // padded row length (bf16 elems)
#define OFF_AH 0
#define OFF_AL (128*80)                 // 10240
#define OFF_BH (2*128*80)               // 20480
#define OFF_BL (2*128*80 + 256*80)      // 40960
#define STAGE_SZ (2*128*80 + 2*256*80)  // 61440
#define GSMEM   (2*STAGE_SZ)            // 122880

__device__ __forceinline__ void g_load_tile(uint32_t sbase, const __nv_bfloat16* g,
                                            int nrows, int row0, int k0, int tid)
{
    const char* gp = (const char*)(g + (size_t)row0 * Hsz + k0);
    for (int c = tid; c < nrows * 4; c += 256) {
        int row = c >> 2, ch = c & 3;
        CP_ASYNC16(sbase + row * 80 + ch * 16, gp + (size_t)row * (Hsz * 2) + ch * 16);
    }
}

__global__ void __launch_bounds__(256, 1)
gemm_mma3(const __nv_bfloat16* __restrict__ Ah, const __nv_bfloat16* __restrict__ Al,
          const __nv_bfloat16* __restrict__ Bh, const __nv_bfloat16* __restrict__ Bl,
          const float* __restrict__ bias, float* __restrict__ C)
{
    extern __shared__ __align__(128) char sm[];
    const uint32_t sb = smem_u32(sm);
    const int tid  = threadIdx.x;
    const int lane = tid & 31;
    const int wid  = tid >> 5;
    const int wm   = wid >> 2;        // 0..1  (m)
    const int wn   = wid & 3;         // 0..3  (n)
    const int bm = blockIdx.y * 128;
    const int bn = blockIdx.x * 256;

    float acc[4][8][4];
    #pragma unroll
    for (int i = 0; i < 4; i++)
        #pragma unroll
        for (int j = 0; j < 8; j++)
            #pragma unroll
            for (int t = 0; t < 4; t++) acc[i][j][t] = 0.f;

    // prologue
    {
        uint32_t st = sb;
        g_load_tile(st + OFF_AH, Ah, 128, bm, 0, tid);
        g_load_tile(st + OFF_AL, Al, 128, bm, 0, tid);
        g_load_tile(st + OFF_BH, Bh, 256, bn, 0, tid);
        g_load_tile(st + OFF_BL, Bl, 256, bn, 0, tid);
        CP_COMMIT();
    }

    // ldmatrix lane-address components
    const int a_row = lane & 15;              // m within tile
    const int a_kb  = (lane >> 4) * 16;       // k byte offset (0/16)
    const int b_row = ((lane >> 4) & 1) * 8 + (lane & 7);  // n within 16-row group
    const int b_kb  = ((lane >> 3) & 1) * 16;

    for (int kt = 0; kt < 64; kt++) {
        const int s = kt & 1;
        if (kt + 1 < 64) {
            uint32_t st = sb + (s ^ 1) * STAGE_SZ;
            int k0 = (kt + 1) * 32;
            g_load_tile(st + OFF_AH, Ah, 128, bm, k0, tid);
            g_load_tile(st + OFF_AL, Al, 128, bm, k0, tid);
            g_load_tile(st + OFF_BH, Bh, 256, bn, k0, tid);
            g_load_tile(st + OFF_BL, Bl, 256, bn, k0, tid);
            CP_COMMIT();
            CP_WAIT(1);
        } else {
            CP_WAIT(0);
        }
        __syncthreads();

        const uint32_t st = sb + s * STAGE_SZ;
        #pragma unroll
        for (int kk = 0; kk < 2; kk++) {
            uint32_t ah[4][4], al[4][4];
            #pragma unroll
            for (int mi = 0; mi < 4; mi++) {
                uint32_t ra = (uint32_t)((wm * 64 + mi * 16 + a_row) * 80 + a_kb + kk * 32);
                ldsm4(ah[mi], st + OFF_AH + ra);
                ldsm4(al[mi], st + OFF_AL + ra);
            }
            #pragma unroll
            for (int half = 0; half < 2; half++) {
                uint32_t bh[2][4], bl[2][4];
                #pragma unroll
                for (int g = 0; g < 2; g++) {
                    uint32_t rb = (uint32_t)((wn * 64 + half * 32 + g * 16 + b_row) * 80
                                             + b_kb + kk * 32);
                    ldsm4(bh[g], st + OFF_BH + rb);
                    ldsm4(bl[g], st + OFF_BL + rb);
                }
                // pass-outer: hh, hl, lh — 16 independent MMAs between acc reuses
                #pragma unroll
                for (int p = 0; p < 3; p++) {
                    #pragma unroll
                    for (int mi = 0; mi < 4; mi++) {
                        #pragma unroll
                        for (int t = 0; t < 4; t++) {
                            const int g = t >> 1, hsel = t & 1;
                            const uint32_t* af = (p == 2) ? al[mi] : ah[mi];
                            const uint32_t* bf = (p == 1) ? bl[g] : bh[g];
                            mma16816(acc[mi][half * 4 + t], af, bf[hsel * 2], bf[hsel * 2 + 1]);
                        }
                    }
                }
            }
        }
        __syncthreads();
    }

    // epilogue
    const int rbase = bm + wm * 64 + (lane >> 2);
    const int cbase = bn + wn * 64 + (lane & 3) * 2;
    #pragma unroll
    for (int mi = 0; mi < 4; mi++) {
        #pragma unroll
        for (int nj = 0; nj < 8; nj++) {
            int row = rbase + mi * 16;
            int col = cbase + nj * 8;
            float b0 = __ldg(&bias[col]), b1 = __ldg(&bias[col + 1]);
            float* c = acc[mi][nj];
            *(float2*)(C + (size_t)row * Hsz + col) = make_float2(c[0] + b0, c[1] + b1);
            *(float2*)(C + (size_t)(row + 8) * Hsz + col) = make_float2(c[2] + b0, c[3] + b1);
        }
    }
}

// ============================================================
// Flash attention, fp32, causal. BQ=BKV=64, D=128, 256 threads.
// ============================================================
#define KST 66

__global__ void __launch_bounds__(256, 2)
flash_attn(const float* __restrict__ Qg, const float* __restrict__ Kg,
           const float* __restrict__ Vg, float* __restrict__ Og)
{
    extern __shared__ float smf[];
    float* sQ  = smf;
    float* sKV = smf + 64 * 128;
    float* sP  = sKV + 128 * KST;

    const int tid = threadIdx.x;
    const int tx = tid & 15;
    const int ty = tid >> 4;
    const int qb = blockIdx.x;
    const int h  = blockIdx.y;
    const int b  = blockIdx.z;
    const int q0 = qb * 64;
    const size_t base = (size_t)b * Ssz * Hsz + (size_t)h * HDIM;

    for (int i = tid * 4; i < 64 * 128; i += 1024) {
        int r = i >> 7, d = i & 127;
        *(float4*)&sQ[i] = *(const float4*)&Qg[base + (size_t)(q0 + r) * Hsz + d];
    }

    u64 o2[4][4];
    #pragma unroll
    for (int i = 0; i < 4; i++)
        #pragma unroll
        for (int j = 0; j < 4; j++) o2[i][j] = 0ull;
    float m_i[4], l_i[4];
    #pragma unroll
    for (int i = 0; i < 4; i++) { m_i[i] = -1e30f; l_i[i] = 0.f; }

    for (int kt = 0; kt <= qb; kt++) {
        __syncthreads();
        for (int i = tid; i < 64 * 128; i += 256) {
            int r = i >> 7, d = i & 127;
            sKV[d * KST + r] = Kg[base + (size_t)(kt * 64 + r) * Hsz + d];
        }
        __syncthreads();

        u64 s2[4][2];
        #pragma unroll
        for (int i = 0; i < 4; i++) { s2[i][0] = 0ull; s2[i][1] = 0ull; }
        #pragma unroll 4
        for (int d = 0; d < 128; d++) {
            u64 k0 = *(const u64*)&sKV[d * KST + tx * 4];
            u64 k1 = *(const u64*)&sKV[d * KST + tx * 4 + 2];
            const float* qp = &sQ[(ty * 4) * 128 + d];
            #pragma unroll
            for (int i = 0; i < 4; i++) {
                u64 qd = dup2(qp[i * 128]);
                ffma2(s2[i][0], qd, k0);
                ffma2(s2[i][1], qd, k1);
            }
        }

        float s[4][4];
        const float sc = 0.08838834764831845f;
        #pragma unroll
        for (int i = 0; i < 4; i++) {
            upk2(s2[i][0], s[i][0], s[i][1]);
            upk2(s2[i][1], s[i][2], s[i][3]);
            #pragma unroll
            for (int j = 0; j < 4; j++) s[i][j] *= sc;
        }
        if (kt == qb) {
            #pragma unroll
            for (int i = 0; i < 4; i++)
                #pragma unroll
                for (int j = 0; j < 4; j++)
                    if (tx * 4 + j > ty * 4 + i) s[i][j] = -1e30f;
        }

        float fac[4];
        #pragma unroll
        for (int i = 0; i < 4; i++) {
            float rm = fmaxf(fmaxf(s[i][0], s[i][1]), fmaxf(s[i][2], s[i][3]));
            #pragma unroll
            for (int off = 8; off > 0; off >>= 1)
                rm = fmaxf(rm, __shfl_xor_sync(0xffffffffu, rm, off));
            float mn = fmaxf(m_i[i], rm);
            fac[i] = __expf(m_i[i] - mn);
            float rs = 0.f;
            #pragma unroll
            for (int j = 0; j < 4; j++) { s[i][j] = __expf(s[i][j] - mn); rs += s[i][j]; }
            #pragma unroll
            for (int off = 8; off > 0; off >>= 1)
                rs += __shfl_xor_sync(0xffffffffu, rs, off);
            l_i[i] = l_i[i] * fac[i] + rs;
            m_i[i] = mn;
        }

        #pragma unroll
        for (int i = 0; i < 4; i++) {
            *(float4*)&sP[(ty * 4 + i) * 64 + tx * 4] =
                make_float4(s[i][0], s[i][1], s[i][2], s[i][3]);
            u64 fd = dup2(fac[i]);
            #pragma unroll
            for (int j = 0; j < 4; j++) fmul2(o2[i][j], fd);
        }
        __syncthreads();

        for (int i = tid * 4; i < 64 * 128; i += 1024) {
            int r = i >> 7, d = i & 127;
            *(float4*)&sKV[r * 128 + d] =
                *(const float4*)&Vg[base + (size_t)(kt * 64 + r) * Hsz + d];
        }
        __syncthreads();

        #pragma unroll 2
        for (int j = 0; j < 64; j++) {
            ulonglong2 v0 = *(const ulonglong2*)&sKV[j * 128 + tx * 4];
            ulonglong2 v1 = *(const ulonglong2*)&sKV[j * 128 + 64 + tx * 4];
            const float* pp = &sP[(ty * 4) * 64 + j];
            #pragma unroll
            for (int i = 0; i < 4; i++) {
                u64 pd = dup2(pp[i * 64]);
                ffma2(o2[i][0], pd, v0.x);
                ffma2(o2[i][1], pd, v0.y);
                ffma2(o2[i][2], pd, v1.x);
                ffma2(o2[i][3], pd, v1.y);
            }
        }
    }

    #pragma unroll
    for (int i = 0; i < 4; i++) {
        float inv = 1.0f / l_i[i];
        size_t rowoff = base + (size_t)(q0 + ty * 4 + i) * Hsz;
        float4 w;
        upk2(o2[i][0], w.x, w.y); upk2(o2[i][1], w.z, w.w);
        w.x *= inv; w.y *= inv; w.z *= inv; w.w *= inv;
        *(float4*)&Og[rowoff + tx * 4] = w;
        upk2(o2[i][2], w.x, w.y); upk2(o2[i][3], w.z, w.w);
        w.x *= inv; w.y *= inv; w.z *= inv; w.w *= inv;
        *(float4*)&Og[rowoff + 64 + tx * 4] = w;
    }
}

// ============================================================
extern "C" void kernel_launch(void* const* d_in, const int* in_sizes, int n_in,
                              void* d_out, int out_size) {
    const float* x  = (const float*)d_in[0];
    const float* Wf[4] = { (const float*)d_in[1], (const float*)d_in[3],
                           (const float*)d_in[5], (const float*)d_in[7] };
    const float* bQ = (const float*)d_in[2];
    const float* bK = (const float*)d_in[4];
    const float* bV = (const float*)d_in[6];
    const float* bO = (const float*)d_in[8];
    float* out = (float*)d_out;

    float *qp, *kp, *vp, *ap;
    cudaGetSymbolAddress((void**)&qp, g_Q);
    cudaGetSymbolAddress((void**)&kp, g_K);
    cudaGetSymbolAddress((void**)&vp, g_V);
    cudaGetSymbolAddress((void**)&ap, g_AO);
    __nv_bfloat16 *xh, *xl, *aoh, *aol, *wh, *wl;
    cudaGetSymbolAddress((void**)&xh,  g_xh);
    cudaGetSymbolAddress((void**)&xl,  g_xl);
    cudaGetSymbolAddress((void**)&aoh, g_aoh);
    cudaGetSymbolAddress((void**)&aol, g_aol);
    cudaGetSymbolAddress((void**)&wh,  g_wh);
    cudaGetSymbolAddress((void**)&wl,  g_wl);

    split_bf16<<<2048, 256>>>((const float4*)x, (__nv_bfloat162*)xh,
                              (__nv_bfloat162*)xl, Mrows * Hsz / 4);
    for (int i = 0; i < 4; i++)
        split_bf16<<<2048, 256>>>((const float4*)Wf[i],
                                  (__nv_bfloat162*)(wh + (size_t)i * Hsz * Hsz),
                                  (__nv_bfloat162*)(wl + (size_t)i * Hsz * Hsz),
                                  Hsz * Hsz / 4);

    cudaFuncSetAttribute(gemm_mma3, cudaFuncAttributeMaxDynamicSharedMemorySize, GSMEM);
    dim3 gg(Hsz / 256, Mrows / 128);
    gemm_mma3<<<gg, 256, GSMEM>>>(xh, xl, wh + 0ull * Hsz * Hsz, wl + 0ull * Hsz * Hsz, bQ, qp);
    gemm_mma3<<<gg, 256, GSMEM>>>(xh, xl, wh + 1ull * Hsz * Hsz, wl + 1ull * Hsz * Hsz, bK, kp);
    gemm_mma3<<<gg, 256, GSMEM>>>(xh, xl, wh + 2ull * Hsz * Hsz, wl + 2ull * Hsz * Hsz, bV, vp);

    const int smbytes = (64 * 128 + 128 * KST + 64 * 64) * 4;
    cudaFuncSetAttribute(flash_attn, cudaFuncAttributeMaxDynamicSharedMemorySize, smbytes);
    flash_attn<<<dim3(Ssz / 64, NHEAD, Bsz), 256, smbytes>>>(qp, kp, vp, ap);

    split_bf16<<<2048, 256>>>((const float4*)ap, (__nv_bfloat162*)aoh,
                              (__nv_bfloat162*)aol, Mrows * Hsz / 4);
    gemm_mma3<<<gg, 256, GSMEM>>>(aoh, aol, wh + 3ull * Hsz * Hsz, wl + 3ull * Hsz * Hsz, bO, out);
}

// round 4
// speedup vs baseline: 2.3924x; 1.5003x over previous
#include <cuda_runtime.h>
#include <cuda_bf16.h>
#include <cstdint>

// Problem dims
#define Bsz   2
#define Ssz   2048
#define Hsz   2048
#define NHEAD 16
#define HDIM  128
#define Mrows (Bsz*Ssz)   // 4096

typedef __nv_bfloat16 bf16;

// ---------------- scratch (static device globals) ----------------
__device__ bf16 g_xh [Mrows*Hsz], g_xl [Mrows*Hsz];
__device__ bf16 g_qh [Mrows*Hsz], g_ql [Mrows*Hsz];
__device__ bf16 g_kh [Mrows*Hsz], g_kl [Mrows*Hsz];
__device__ bf16 g_vh [Mrows*Hsz], g_vl [Mrows*Hsz];
__device__ bf16 g_aoh[Mrows*Hsz], g_aol[Mrows*Hsz];
__device__ bf16 g_wh [4][Hsz*Hsz], g_wl [4][Hsz*Hsz];

// ---------------- helpers ----------------
__device__ __forceinline__ uint32_t smem_u32(const void* p) {
    uint32_t a;
    asm("{ .reg .u64 t; cvta.to.shared.u64 t, %1; cvt.u32.u64 %0, t; }" : "=r"(a) : "l"(p));
    return a;
}
#define CP_ASYNC16(sa, ga) \
    asm volatile("cp.async.cg.shared.global [%0], [%1], 16;" :: "r"((uint32_t)(sa)), "l"(ga))
#define CP_COMMIT() asm volatile("cp.async.commit_group;" ::: "memory")
#define CP_WAIT(n)  asm volatile("cp.async.wait_group %0;" :: "n"(n) : "memory")

__device__ __forceinline__ void ldsm4(uint32_t* r, uint32_t addr) {
    asm volatile("ldmatrix.sync.aligned.m8n8.x4.shared.b16 {%0,%1,%2,%3}, [%4];"
                 : "=r"(r[0]), "=r"(r[1]), "=r"(r[2]), "=r"(r[3]) : "r"(addr));
}
__device__ __forceinline__ void ldsm4t(uint32_t* r, uint32_t addr) {
    asm volatile("ldmatrix.sync.aligned.m8n8.x4.trans.shared.b16 {%0,%1,%2,%3}, [%4];"
                 : "=r"(r[0]), "=r"(r[1]), "=r"(r[2]), "=r"(r[3]) : "r"(addr));
}
__device__ __forceinline__ void mma16816(float* c, const uint32_t* a,
                                         uint32_t b0, uint32_t b1) {
    asm volatile(
        "mma.sync.aligned.m16n8k16.row.col.f32.bf16.bf16.f32 "
        "{%0,%1,%2,%3}, {%4,%5,%6,%7}, {%8,%9}, {%0,%1,%2,%3};"
        : "+f"(c[0]), "+f"(c[1]), "+f"(c[2]), "+f"(c[3])
        : "r"(a[0]), "r"(a[1]), "r"(a[2]), "r"(a[3]), "r"(b0), "r"(b1));
}
// split two floats into packed bf16x2 hi and lo
__device__ __forceinline__ void split2(float a, float b, uint32_t& hi, uint32_t& lo) {
    bf16 ha = __float2bfloat16(a), hb = __float2bfloat16(b);
    bf16 la = __float2bfloat16(a - __bfloat162float(ha));
    bf16 lb = __float2bfloat16(b - __bfloat162float(hb));
    __nv_bfloat162 h(ha, hb), l(la, lb);
    hi = *(uint32_t*)&h; lo = *(uint32_t*)&l;
}

// ============================================================
// split fp32 -> (bf16 hi, bf16 lo)   (for x and weights)
// ============================================================
__global__ void split_bf16(const float4* __restrict__ in,
                           __nv_bfloat162* __restrict__ hi,
                           __nv_bfloat162* __restrict__ lo, int n4)
{
    for (int i = blockIdx.x * blockDim.x + threadIdx.x; i < n4; i += gridDim.x * blockDim.x) {
        float4 v = in[i];
        uint32_t h0, l0, h1, l1;
        split2(v.x, v.y, h0, l0);
        split2(v.z, v.w, h1, l1);
        ((uint32_t*)hi)[2*i] = h0; ((uint32_t*)hi)[2*i+1] = h1;
        ((uint32_t*)lo)[2*i] = l0; ((uint32_t*)lo)[2*i+1] = l1;
    }
}

// ============================================================
// mma.sync GEMM: C[4096, 2048] = A @ B^T + bias  (3-pass bf16 split)
// CTA tile 128x256, BK=32, 8 warps 2x4, warp tile 64x64.
// BF16OUT: write (hi,lo) bf16 pair instead of fp32.
// ============================================================
#define OFF_AH 0
#define OFF_AL (128*80)
#define OFF_BH (2*128*80)
#define OFF_BL (2*128*80 + 256*80)
#define STAGE_SZ (2*128*80 + 2*256*80)
#define GSMEM   (2*STAGE_SZ)

__device__ __forceinline__ void g_load_tile(uint32_t sbase, const bf16* g,
                                            int nrows, int row0, int k0, int tid)
{
    const char* gp = (const char*)(g + (size_t)row0 * Hsz + k0);
    for (int c = tid; c < nrows * 4; c += 256) {
        int row = c >> 2, ch = c & 3;
        CP_ASYNC16(sbase + row * 80 + ch * 16, gp + (size_t)row * (Hsz * 2) + ch * 16);
    }
}

template <bool BF16OUT>
__global__ void __launch_bounds__(256, 1)
gemm_mma3(const bf16* __restrict__ Ah, const bf16* __restrict__ Al,
          const bf16* __restrict__ Bh, const bf16* __restrict__ Bl,
          const float* __restrict__ bias, float* __restrict__ C,
          bf16* __restrict__ Ch, bf16* __restrict__ Cl)
{
    extern __shared__ __align__(128) char sm[];
    const uint32_t sb = smem_u32(sm);
    const int tid  = threadIdx.x;
    const int lane = tid & 31;
    const int wid  = tid >> 5;
    const int wm   = wid >> 2;
    const int wn   = wid & 3;
    const int bm = blockIdx.y * 128;
    const int bn = blockIdx.x * 256;

    float acc[4][8][4];
    #pragma unroll
    for (int i = 0; i < 4; i++)
        #pragma unroll
        for (int j = 0; j < 8; j++)
            #pragma unroll
            for (int t = 0; t < 4; t++) acc[i][j][t] = 0.f;

    {
        g_load_tile(sb + OFF_AH, Ah, 128, bm, 0, tid);
        g_load_tile(sb + OFF_AL, Al, 128, bm, 0, tid);
        g_load_tile(sb + OFF_BH, Bh, 256, bn, 0, tid);
        g_load_tile(sb + OFF_BL, Bl, 256, bn, 0, tid);
        CP_COMMIT();
    }

    const int a_row = lane & 15;
    const int a_kb  = (lane >> 4) * 16;
    const int b_row = ((lane >> 4) & 1) * 8 + (lane & 7);
    const int b_kb  = ((lane >> 3) & 1) * 16;

    for (int kt = 0; kt < 64; kt++) {
        const int s = kt & 1;
        if (kt + 1 < 64) {
            uint32_t st = sb + (s ^ 1) * STAGE_SZ;
            int k0 = (kt + 1) * 32;
            g_load_tile(st + OFF_AH, Ah, 128, bm, k0, tid);
            g_load_tile(st + OFF_AL, Al, 128, bm, k0, tid);
            g_load_tile(st + OFF_BH, Bh, 256, bn, k0, tid);
            g_load_tile(st + OFF_BL, Bl, 256, bn, k0, tid);
            CP_COMMIT();
            CP_WAIT(1);
        } else {
            CP_WAIT(0);
        }
        __syncthreads();

        const uint32_t st = sb + s * STAGE_SZ;
        #pragma unroll
        for (int kk = 0; kk < 2; kk++) {
            uint32_t ah[4][4], al[4][4];
            #pragma unroll
            for (int mi = 0; mi < 4; mi++) {
                uint32_t ra = (uint32_t)((wm * 64 + mi * 16 + a_row) * 80 + a_kb + kk * 32);
                ldsm4(ah[mi], st + OFF_AH + ra);
                ldsm4(al[mi], st + OFF_AL + ra);
            }
            #pragma unroll
            for (int half = 0; half < 2; half++) {
                uint32_t bh[2][4], bl[2][4];
                #pragma unroll
                for (int g = 0; g < 2; g++) {
                    uint32_t rb = (uint32_t)((wn * 64 + half * 32 + g * 16 + b_row) * 80
                                             + b_kb + kk * 32);
                    ldsm4(bh[g], st + OFF_BH + rb);
                    ldsm4(bl[g], st + OFF_BL + rb);
                }
                #pragma unroll
                for (int p = 0; p < 3; p++) {
                    #pragma unroll
                    for (int mi = 0; mi < 4; mi++) {
                        #pragma unroll
                        for (int t = 0; t < 4; t++) {
                            const int g = t >> 1, hsel = t & 1;
                            const uint32_t* af = (p == 2) ? al[mi] : ah[mi];
                            const uint32_t* bf = (p == 1) ? bl[g] : bh[g];
                            mma16816(acc[mi][half * 4 + t], af, bf[hsel * 2], bf[hsel * 2 + 1]);
                        }
                    }
                }
            }
        }
        __syncthreads();
    }

    const int rbase = bm + wm * 64 + (lane >> 2);
    const int cbase = bn + wn * 64 + (lane & 3) * 2;
    #pragma unroll
    for (int mi = 0; mi < 4; mi++) {
        #pragma unroll
        for (int nj = 0; nj < 8; nj++) {
            int row = rbase + mi * 16;
            int col = cbase + nj * 8;
            float b0 = __ldg(&bias[col]), b1 = __ldg(&bias[col + 1]);
            float* c = acc[mi][nj];
            float v00 = c[0] + b0, v01 = c[1] + b1;
            float v10 = c[2] + b0, v11 = c[3] + b1;
            if (BF16OUT) {
                uint32_t h, l;
                split2(v00, v01, h, l);
                *(uint32_t*)(Ch + (size_t)row * Hsz + col) = h;
                *(uint32_t*)(Cl + (size_t)row * Hsz + col) = l;
                split2(v10, v11, h, l);
                *(uint32_t*)(Ch + (size_t)(row + 8) * Hsz + col) = h;
                *(uint32_t*)(Cl + (size_t)(row + 8) * Hsz + col) = l;
            } else {
                *(float2*)(C + (size_t)row * Hsz + col) = make_float2(v00, v01);
                *(float2*)(C + (size_t)(row + 8) * Hsz + col) = make_float2(v10, v11);
            }
        }
    }
}

// ============================================================
// Flash attention via mma.sync, 3-pass split on QK and PV.
// BQ=128, BKV=64, 256 threads (8 warps x 16 query rows).
// Q frags register-resident; K,V single-buffer with cross-overlap.
// ============================================================
#define VST 272                 // smem row stride bytes (conflict-free, 16B-aligned)
#define AKH 0
#define AKL (64*VST)            // 17408
#define AVH (2*64*VST)          // 34816
#define AVL (3*64*VST)          // 52224
#define ASMEM (4*64*VST)        // 69632

__device__ __forceinline__ void fa_load64(uint32_t sbase, const bf16* g, size_t gelem, int tid) {
    const char* gp = (const char*)(g + gelem);
    for (int c = tid; c < 1024; c += 256) {
        int r = c >> 4, ch = c & 15;
        CP_ASYNC16(sbase + r * VST + ch * 16, gp + (size_t)r * (Hsz * 2) + ch * 16);
    }
}
__device__ __forceinline__ void fa_load128(uint32_t sbase, const bf16* g, size_t gelem, int tid) {
    const char* gp = (const char*)(g + gelem);
    for (int c = tid; c < 2048; c += 256) {
        int r = c >> 4, ch = c & 15;
        CP_ASYNC16(sbase + r * VST + ch * 16, gp + (size_t)r * (Hsz * 2) + ch * 16);
    }
}

__global__ void __launch_bounds__(256, 1)
flash_mma(const bf16* __restrict__ Qh, const bf16* __restrict__ Ql,
          const bf16* __restrict__ Kh, const bf16* __restrict__ Kl,
          const bf16* __restrict__ Vh, const bf16* __restrict__ Vl,
          bf16* __restrict__ AOh, bf16* __restrict__ AOl)
{
    extern __shared__ __align__(128) char sm[];
    const uint32_t sb = smem_u32(sm);
    const int tid = threadIdx.x;
    const int lane = tid & 31;
    const int w = tid >> 5;
    const int wrow = w * 16;
    const int qb = blockIdx.x, h = blockIdx.y, b = blockIdx.z;
    const int q0 = qb * 128;
    const size_t baseKV = (size_t)(b * Ssz) * Hsz + h * HDIM;
    const size_t baseQ  = baseKV + (size_t)q0 * Hsz;

    const int a_row = lane & 15;
    const int a_kb  = (lane >> 4) * 16;
    const int b_row = ((lane >> 4) & 1) * 8 + (lane & 7);
    const int b_kb  = ((lane >> 3) & 1) * 16;
    const int t_row = lane & 15;            // trans-ldmatrix row (k)
    const int t_cb  = (lane >> 4) * 16;     // trans col byte within 32B pair

    // ---- load Q fragments (hi then lo) via smem staging in K area ----
    uint32_t qfh[8][4], qfl[8][4];
    fa_load128(sb, Qh, baseQ, tid); CP_COMMIT(); CP_WAIT(0); __syncthreads();
    #pragma unroll
    for (int t = 0; t < 8; t++)
        ldsm4(qfh[t], sb + (uint32_t)((wrow + a_row) * VST + a_kb + t * 32));
    __syncthreads();
    fa_load128(sb, Ql, baseQ, tid); CP_COMMIT(); CP_WAIT(0); __syncthreads();
    #pragma unroll
    for (int t = 0; t < 8; t++)
        ldsm4(qfl[t], sb + (uint32_t)((wrow + a_row) * VST + a_kb + t * 32));
    __syncthreads();

    // kick off K(0)
    fa_load64(sb + AKH, Kh, baseKV, tid);
    fa_load64(sb + AKL, Kl, baseKV, tid);
    CP_COMMIT();

    float o[16][4];
    #pragma unroll
    for (int j = 0; j < 16; j++)
        #pragma unroll
        for (int t = 0; t < 4; t++) o[j][t] = 0.f;
    float m_i[2] = {-1e30f, -1e30f}, l_i[2] = {0.f, 0.f};

    const int ktmax = 2 * qb + 1;
    const int r0 = lane >> 2;
    const float sc = 0.08838834764831845f;   // 1/sqrt(128)

    for (int kt = 0; kt <= ktmax; kt++) {
        // V(kt) load overlaps QK compute
        fa_load64(sb + AVH, Vh, baseKV + (size_t)(kt * 64) * Hsz, tid);
        fa_load64(sb + AVL, Vl, baseKV + (size_t)(kt * 64) * Hsz, tid);
        CP_COMMIT();
        CP_WAIT(1);              // K(kt) complete
        __syncthreads();

        const bool active = (kt * 64 <= q0 + wrow + 15);
        float s[8][4];
        if (active) {
            #pragma unroll
            for (int j = 0; j < 8; j++)
                #pragma unroll
                for (int t = 0; t < 4; t++) s[j][t] = 0.f;
            #pragma unroll
            for (int t = 0; t < 8; t++) {
                uint32_t kbh[4][4], kbl[4][4];
                #pragma unroll
                for (int p = 0; p < 4; p++) {
                    uint32_t ra = (uint32_t)((p * 16 + b_row) * VST + b_kb + t * 32);
                    ldsm4(kbh[p], sb + AKH + ra);
                    ldsm4(kbl[p], sb + AKL + ra);
                }
                #pragma unroll
                for (int p = 0; p < 4; p++) {
                    #pragma unroll
                    for (int hh = 0; hh < 2; hh++) {
                        mma16816(s[2*p+hh], qfh[t], kbh[p][hh*2], kbh[p][hh*2+1]);
                        mma16816(s[2*p+hh], qfh[t], kbl[p][hh*2], kbl[p][hh*2+1]);
                        mma16816(s[2*p+hh], qfl[t], kbh[p][hh*2], kbh[p][hh*2+1]);
                    }
                }
            }
        }
        __syncthreads();         // everyone done reading K buf

        const bool more = kt < ktmax;
        if (more) {
            fa_load64(sb + AKH, Kh, baseKV + (size_t)((kt + 1) * 64) * Hsz, tid);
            fa_load64(sb + AKL, Kl, baseKV + (size_t)((kt + 1) * 64) * Hsz, tid);
            CP_COMMIT();
        }

        uint32_t pah[4][4], pal[4][4];
        float fac[2];
        if (active) {
            // scale + causal mask
            #pragma unroll
            for (int j = 0; j < 8; j++)
                #pragma unroll
                for (int t = 0; t < 4; t++) s[j][t] *= sc;
            if (kt * 64 + 63 > q0 + wrow) {
                #pragma unroll
                for (int j = 0; j < 8; j++) {
                    int col = kt * 64 + j * 8 + (lane & 3) * 2;
                    int row = q0 + wrow + r0;
                    if (col > row)          s[j][0] = -1e30f;
                    if (col + 1 > row)      s[j][1] = -1e30f;
                    if (col > row + 8)      s[j][2] = -1e30f;
                    if (col + 1 > row + 8)  s[j][3] = -1e30f;
                }
            }
            // online softmax (two rows per thread, quad reduction)
            #pragma unroll
            for (int r = 0; r < 2; r++) {
                float rm = -1e30f;
                #pragma unroll
                for (int j = 0; j < 8; j++) rm = fmaxf(rm, fmaxf(s[j][r*2], s[j][r*2+1]));
                rm = fmaxf(rm, __shfl_xor_sync(0xffffffffu, rm, 1));
                rm = fmaxf(rm, __shfl_xor_sync(0xffffffffu, rm, 2));
                float mn = fmaxf(m_i[r], rm);
                fac[r] = __expf(m_i[r] - mn);
                float rs = 0.f;
                #pragma unroll
                for (int j = 0; j < 8; j++) {
                    s[j][r*2]   = __expf(s[j][r*2]   - mn);
                    s[j][r*2+1] = __expf(s[j][r*2+1] - mn);
                    rs += s[j][r*2] + s[j][r*2+1];
                }
                rs += __shfl_xor_sync(0xffffffffu, rs, 1);
                rs += __shfl_xor_sync(0xffffffffu, rs, 2);
                l_i[r] = l_i[r] * fac[r] + rs;
                m_i[r] = mn;
            }
            // repack P fragments (C -> A layout), hi/lo split
            #pragma unroll
            for (int t2 = 0; t2 < 4; t2++) {
                split2(s[2*t2][0],   s[2*t2][1],   pah[t2][0], pal[t2][0]);
                split2(s[2*t2][2],   s[2*t2][3],   pah[t2][1], pal[t2][1]);
                split2(s[2*t2+1][0], s[2*t2+1][1], pah[t2][2], pal[t2][2]);
                split2(s[2*t2+1][2], s[2*t2+1][3], pah[t2][3], pal[t2][3]);
            }
            // rescale O
            #pragma unroll
            for (int j = 0; j < 16; j++) {
                o[j][0] *= fac[0]; o[j][1] *= fac[0];
                o[j][2] *= fac[1]; o[j][3] *= fac[1];
            }
        }

        if (more) { CP_WAIT(1); } else { CP_WAIT(0); }   // V(kt) complete
        __syncthreads();

        if (active) {
            #pragma unroll
            for (int j2 = 0; j2 < 8; j2++) {
                #pragma unroll
                for (int t = 0; t < 4; t++) {
                    uint32_t bvh[4], bvl[4];
                    uint32_t ra = (uint32_t)((t * 16 + t_row) * VST + t_cb + j2 * 32);
                    ldsm4t(bvh, sb + AVH + ra);
                    ldsm4t(bvl, sb + AVL + ra);
                    mma16816(o[2*j2],   pah[t], bvh[0], bvh[1]);
                    mma16816(o[2*j2+1], pah[t], bvh[2], bvh[3]);
                    mma16816(o[2*j2],   pah[t], bvl[0], bvl[1]);
                    mma16816(o[2*j2+1], pah[t], bvl[2], bvl[3]);
                    mma16816(o[2*j2],   pal[t], bvh[0], bvh[1]);
                    mma16816(o[2*j2+1], pal[t], bvh[2], bvh[3]);
                }
            }
        }
        __syncthreads();         // everyone done reading V buf
    }

    // epilogue: normalize, split to bf16 hi/lo, store
    const float inv0 = 1.0f / l_i[0], inv1 = 1.0f / l_i[1];
    const int grow0 = q0 + wrow + r0;
    #pragma unroll
    for (int j = 0; j < 16; j++) {
        int col = j * 8 + (lane & 3) * 2;
        size_t e0 = baseKV + (size_t)grow0 * Hsz + col;
        size_t e1 = baseKV + (size_t)(grow0 + 8) * Hsz + col;
        uint32_t hh, ll;
        split2(o[j][0] * inv0, o[j][1] * inv0, hh, ll);
        *(uint32_t*)(AOh + e0) = hh; *(uint32_t*)(AOl + e0) = ll;
        split2(o[j][2] * inv1, o[j][3] * inv1, hh, ll);
        *(uint32_t*)(AOh + e1) = hh; *(uint32_t*)(AOl + e1) = ll;
    }
}

// ============================================================
extern "C" void kernel_launch(void* const* d_in, const int* in_sizes, int n_in,
                              void* d_out, int out_size) {
    const float* x  = (const float*)d_in[0];
    const float* Wf[4] = { (const float*)d_in[1], (const float*)d_in[3],
                           (const float*)d_in[5], (const float*)d_in[7] };
    const float* bQ = (const float*)d_in[2];
    const float* bK = (const float*)d_in[4];
    const float* bV = (const float*)d_in[6];
    const float* bO = (const float*)d_in[8];
    float* out = (float*)d_out;

    bf16 *xh, *xl, *qh, *ql, *kh, *kl, *vh, *vl, *aoh, *aol, *wh, *wl;
    cudaGetSymbolAddress((void**)&xh,  g_xh);  cudaGetSymbolAddress((void**)&xl,  g_xl);
    cudaGetSymbolAddress((void**)&qh,  g_qh);  cudaGetSymbolAddress((void**)&ql,  g_ql);
    cudaGetSymbolAddress((void**)&kh,  g_kh);  cudaGetSymbolAddress((void**)&kl,  g_kl);
    cudaGetSymbolAddress((void**)&vh,  g_vh);  cudaGetSymbolAddress((void**)&vl,  g_vl);
    cudaGetSymbolAddress((void**)&aoh, g_aoh); cudaGetSymbolAddress((void**)&aol, g_aol);
    cudaGetSymbolAddress((void**)&wh,  g_wh);  cudaGetSymbolAddress((void**)&wl,  g_wl);

    split_bf16<<<2048, 256>>>((const float4*)x, (__nv_bfloat162*)xh,
                              (__nv_bfloat162*)xl, Mrows * Hsz / 4);
    for (int i = 0; i < 4; i++)
        split_bf16<<<2048, 256>>>((const float4*)Wf[i],
                                  (__nv_bfloat162*)(wh + (size_t)i * Hsz * Hsz),
                                  (__nv_bfloat162*)(wl + (size_t)i * Hsz * Hsz),
                                  Hsz * Hsz / 4);

    cudaFuncSetAttribute(gemm_mma3<true>,  cudaFuncAttributeMaxDynamicSharedMemorySize, GSMEM);
    cudaFuncSetAttribute(gemm_mma3<false>, cudaFuncAttributeMaxDynamicSharedMemorySize, GSMEM);
    dim3 gg(Hsz / 256, Mrows / 128);
    gemm_mma3<true><<<gg, 256, GSMEM>>>(xh, xl, wh + 0ull*Hsz*Hsz, wl + 0ull*Hsz*Hsz,
                                        bQ, nullptr, qh, ql);
    gemm_mma3<true><<<gg, 256, GSMEM>>>(xh, xl, wh + 1ull*Hsz*Hsz, wl + 1ull*Hsz*Hsz,
                                        bK, nullptr, kh, kl);
    gemm_mma3<true><<<gg, 256, GSMEM>>>(xh, xl, wh + 2ull*Hsz*Hsz, wl + 2ull*Hsz*Hsz,
                                        bV, nullptr, vh, vl);

    cudaFuncSetAttribute(flash_mma, cudaFuncAttributeMaxDynamicSharedMemorySize, ASMEM);
    flash_mma<<<dim3(Ssz / 128, NHEAD, Bsz), 256, ASMEM>>>(qh, ql, kh, kl, vh, vl, aoh, aol);

    gemm_mma3<false><<<gg, 256, GSMEM>>>(aoh, aol, wh + 3ull*Hsz*Hsz, wl + 3ull*Hsz*Hsz,
                                         bO, out, nullptr, nullptr);
}